// round 17
// baseline (speedup 1.0000x reference)
#include <cuda_runtime.h>

#define XNS 32
#define XNC 16
#define XT  64
#define XNB 512
#define XSC 48
#define QSTRIDE 10368
#define SMEM_BYTES 89088

// gain scratch: per (b,t) 528 floats = [K 16x32][k 16]
__device__ float g_G[(size_t)XNB * XT * 528];

__device__ __forceinline__ void cpa16(void* s, const void* g) {
    unsigned sa = (unsigned)__cvta_generic_to_shared(s);
    asm volatile("cp.async.cg.shared.global [%0], [%1], 16;" :: "r"(sa), "l"(g));
}
__device__ __forceinline__ void cpa_commit() { asm volatile("cp.async.commit_group;"); }
__device__ __forceinline__ void cpa_wait0()  { asm volatile("cp.async.wait_group 0;"); }

// per-batch shared blocks inside dynamic smem (floats):
// sF[1536] | q-block x2: sV 0(1152) sM 1152(1536) sQt 2688(2304) sQraw 4992(2304)
//   scx 7296(2048) sKt 9344(512) skt 9856(16) sqt 9872(48) sv 9920(32)
//   sInv 9952(320) sp 10272(48) scc 10320(48)  -> stride 10368
#define SVq(q)   (smem + 1536 + (q)*QSTRIDE + 0)
#define SMq(q)   (smem + 1536 + (q)*QSTRIDE + 1152)
#define SQTq(q)  (smem + 1536 + (q)*QSTRIDE + 2688)
#define SQRq(q)  (smem + 1536 + (q)*QSTRIDE + 4992)
#define SCXq(q)  (smem + 1536 + (q)*QSTRIDE + 7296)
#define SKTq(q)  (smem + 1536 + (q)*QSTRIDE + 9344)
#define SKtq(q)  (smem + 1536 + (q)*QSTRIDE + 9856)
#define SQtvq(q) (smem + 1536 + (q)*QSTRIDE + 9872)
#define SVvq(q)  (smem + 1536 + (q)*QSTRIDE + 9920)
#define SINVq(q) (smem + 1536 + (q)*QSTRIDE + 9952)
#define SPq(q)   (smem + 1536 + (q)*QSTRIDE + 10272)
#define SCCq(q)  (smem + 1536 + (q)*QSTRIDE + 10320)

// ---- phase bodies (R10-identical math, pointer-parameterized) ----

__device__ __forceinline__ void kt_tile(const float* sInv, const float* sQt,
                                        float* sKt, int lt)
{
    const int a0 = (lt >> 3) * 4, i0 = (lt & 7) * 4;
    float4 r0 = {0,0,0,0}, r1 = {0,0,0,0}, r2 = {0,0,0,0}, r3 = {0,0,0,0};
    #pragma unroll
    for (int c0 = 0; c0 < 16; c0 += 4) {
        const float4 v0 = *(const float4*)(sInv + (a0+0)*20 + c0);
        const float4 v1 = *(const float4*)(sInv + (a0+1)*20 + c0);
        const float4 v2 = *(const float4*)(sInv + (a0+2)*20 + c0);
        const float4 v3 = *(const float4*)(sInv + (a0+3)*20 + c0);
        const float4 q0 = *(const float4*)(sQt + (32+c0+0)*48 + i0);
        const float4 q1 = *(const float4*)(sQt + (32+c0+1)*48 + i0);
        const float4 q2 = *(const float4*)(sQt + (32+c0+2)*48 + i0);
        const float4 q3 = *(const float4*)(sQt + (32+c0+3)*48 + i0);
        r0.x += v0.x*q0.x + v0.y*q1.x + v0.z*q2.x + v0.w*q3.x;
        r0.y += v0.x*q0.y + v0.y*q1.y + v0.z*q2.y + v0.w*q3.y;
        r0.z += v0.x*q0.z + v0.y*q1.z + v0.z*q2.z + v0.w*q3.z;
        r0.w += v0.x*q0.w + v0.y*q1.w + v0.z*q2.w + v0.w*q3.w;
        r1.x += v1.x*q0.x + v1.y*q1.x + v1.z*q2.x + v1.w*q3.x;
        r1.y += v1.x*q0.y + v1.y*q1.y + v1.z*q2.y + v1.w*q3.y;
        r1.z += v1.x*q0.z + v1.y*q1.z + v1.z*q2.z + v1.w*q3.z;
        r1.w += v1.x*q0.w + v1.y*q1.w + v1.z*q2.w + v1.w*q3.w;
        r2.x += v2.x*q0.x + v2.y*q1.x + v2.z*q2.x + v2.w*q3.x;
        r2.y += v2.x*q0.y + v2.y*q1.y + v2.z*q2.y + v2.w*q3.y;
        r2.z += v2.x*q0.z + v2.y*q1.z + v2.z*q2.z + v2.w*q3.z;
        r2.w += v2.x*q0.w + v2.y*q1.w + v2.z*q2.w + v2.w*q3.w;
        r3.x += v3.x*q0.x + v3.y*q1.x + v3.z*q2.x + v3.w*q3.x;
        r3.y += v3.x*q0.y + v3.y*q1.y + v3.z*q2.y + v3.w*q3.y;
        r3.z += v3.x*q0.z + v3.y*q1.z + v3.z*q2.z + v3.w*q3.z;
        r3.w += v3.x*q0.w + v3.y*q1.w + v3.z*q2.w + v3.w*q3.w;
    }
    *(float4*)(sKt + (a0+0)*32 + i0) = make_float4(-r0.x,-r0.y,-r0.z,-r0.w);
    *(float4*)(sKt + (a0+1)*32 + i0) = make_float4(-r1.x,-r1.y,-r1.z,-r1.w);
    *(float4*)(sKt + (a0+2)*32 + i0) = make_float4(-r2.x,-r2.y,-r2.z,-r2.w);
    *(float4*)(sKt + (a0+3)*32 + i0) = make_float4(-r3.x,-r3.y,-r3.z,-r3.w);
}

__device__ __forceinline__ void kt_vec(const float* sInv, const float* sqt,
                                       float* skt, float* scc, int a)
{
    float acc = 0.f;
    #pragma unroll
    for (int cc = 0; cc < 16; cc++) {
        int c = (a + cc) & 15;
        acc += sInv[a*20 + c] * sqt[32 + c];
    }
    skt[a] = -acc;
    scc[32 + a] += -0.5f * sqt[32 + a] * acc;      // 0.5 * qu_a * kt_a
}

__device__ __forceinline__ void vn_tile(const float* sQt, const float* sKt,
                                        float* sV, int lt)
{
    const int g = lt >> 3;
    const int i0 = g * 4, j0 = (lt & 7) * 4;
    float4 v0 = *(const float4*)(sQt + (i0+0)*48 + j0);
    float4 v1 = *(const float4*)(sQt + (i0+1)*48 + j0);
    float4 v2 = *(const float4*)(sQt + (i0+2)*48 + j0);
    float4 v3 = *(const float4*)(sQt + (i0+3)*48 + j0);
    #pragma unroll
    for (int ch = 0; ch < 4; ch++) {
        const int c0 = ((ch + g) & 3) * 4;          // rotate: breaks bank conflicts
        const float4 a0v = *(const float4*)(sQt + (i0+0)*48 + 32 + c0);
        const float4 a1v = *(const float4*)(sQt + (i0+1)*48 + 32 + c0);
        const float4 a2v = *(const float4*)(sQt + (i0+2)*48 + 32 + c0);
        const float4 a3v = *(const float4*)(sQt + (i0+3)*48 + 32 + c0);
        const float4 k0 = *(const float4*)(sKt + (c0+0)*32 + j0);
        const float4 k1 = *(const float4*)(sKt + (c0+1)*32 + j0);
        const float4 k2 = *(const float4*)(sKt + (c0+2)*32 + j0);
        const float4 k3 = *(const float4*)(sKt + (c0+3)*32 + j0);
        v0.x += a0v.x*k0.x + a0v.y*k1.x + a0v.z*k2.x + a0v.w*k3.x;
        v0.y += a0v.x*k0.y + a0v.y*k1.y + a0v.z*k2.y + a0v.w*k3.y;
        v0.z += a0v.x*k0.z + a0v.y*k1.z + a0v.z*k2.z + a0v.w*k3.z;
        v0.w += a0v.x*k0.w + a0v.y*k1.w + a0v.z*k2.w + a0v.w*k3.w;
        v1.x += a1v.x*k0.x + a1v.y*k1.x + a1v.z*k2.x + a1v.w*k3.x;
        v1.y += a1v.x*k0.y + a1v.y*k1.y + a1v.z*k2.y + a1v.w*k3.y;
        v1.z += a1v.x*k0.z + a1v.y*k1.z + a1v.z*k2.z + a1v.w*k3.z;
        v1.w += a1v.x*k0.w + a1v.y*k1.w + a1v.z*k2.w + a1v.w*k3.w;
        v2.x += a2v.x*k0.x + a2v.y*k1.x + a2v.z*k2.x + a2v.w*k3.x;
        v2.y += a2v.x*k0.y + a2v.y*k1.y + a2v.z*k2.y + a2v.w*k3.y;
        v2.z += a2v.x*k0.z + a2v.y*k1.z + a2v.z*k2.z + a2v.w*k3.z;
        v2.w += a2v.x*k0.w + a2v.y*k1.w + a2v.z*k2.w + a2v.w*k3.w;
        v3.x += a3v.x*k0.x + a3v.y*k1.x + a3v.z*k2.x + a3v.w*k3.x;
        v3.y += a3v.x*k0.y + a3v.y*k1.y + a3v.z*k2.y + a3v.w*k3.y;
        v3.z += a3v.x*k0.z + a3v.y*k1.z + a3v.z*k2.z + a3v.w*k3.z;
        v3.w += a3v.x*k0.w + a3v.y*k1.w + a3v.z*k2.w + a3v.w*k3.w;
    }
    *(float4*)(sV + (i0+0)*36 + j0) = v0;
    *(float4*)(sV + (i0+1)*36 + j0) = v1;
    *(float4*)(sV + (i0+2)*36 + j0) = v2;
    *(float4*)(sV + (i0+3)*36 + j0) = v3;
}

__global__ __launch_bounds__(256, 2)
void lqr_kernel(const float* __restrict__ Xi, const float* __restrict__ Qg,
                const float* __restrict__ Pg, const float* __restrict__ Ag,
                const float* __restrict__ Bg, float* __restrict__ out)
{
    extern __shared__ __align__(16) float smem[];
    float* const sF = smem;                         // 32 x 48

    const int b0  = blockIdx.x * 2;
    const int tid = threadIdx.x;
    const int lane = tid & 31;
    const float* Qb[2] = { Qg + (size_t)(b0+0) * XT * XSC * XSC,
                           Qg + (size_t)(b0+1) * XT * XSC * XSC };
    const float* Pb[2] = { Pg + (size_t)(b0+0) * XT * XSC,
                           Pg + (size_t)(b0+1) * XT * XSC };

    // ---- B-phase tile map: 78 lower-tri + 6 upper uu, float4 4x4 (tid<84) ----
    int i0B = 0, j0B = 0;
    if (tid < 78) {
        int e = tid, r = 0;
        while (e >= r + 1) { e -= r + 1; r++; }
        i0B = r * 4; j0B = e * 4;
    } else if (tid < 84) {
        const int q = tid - 78;                     // (8,9)(8,10)(8,11)(9,10)(9,11)(10,11)
        const int rt = (q < 3) ? 8 : ((q < 5) ? 9 : 10);
        const int ct = (q < 3) ? (9 + q) : ((q < 5) ? (7 + q) : 11);
        i0B = rt * 4; j0B = ct * 4;
    }
    // ---- mirror map: 60 strict-upper tiles excl. uu; threads 64..183, q=m/60 ----
    int mSrc = 0, mDst = 0;
    if (tid >= 64 && tid < 184) {
        const int myT = (tid - 64) % 60;
        int cnt = 0;
        for (int rt = 0; rt < 12; rt++)
            for (int ct = rt + 1; ct < 12; ct++) {
                if (rt >= 8 && ct >= 8) continue;
                if (cnt == myT) { mSrc = (ct * 4) * 48 + rt * 4;
                                  mDst = (rt * 4) * 48 + ct * 4; }
                cnt++;
            }
    }

    // ---- setup ----
    for (int e = tid; e < 1536; e += 256) {
        int s = e / 48, j = e % 48;
        sF[e] = (j < 32) ? Ag[s * 32 + j] : Bg[s * 16 + (j - 32)];
    }
    for (int e = tid; e < 2304; e += 256) SVq(e / 1152)[e % 1152] = 0.f;
    if (tid < 64) SVvq(tid >> 5)[lane] = 0.f;
    if (tid < 96) SCCq(tid / 48)[tid % 48] = 0.f;
    {   // prefetch Q(T-1), p(T-1), both batches
        for (int idx = tid; idx < 1152; idx += 256) {
            const int q = idx / 576, i2 = idx % 576;
            cpa16(SQRq(q) + i2 * 4, Qb[q] + (size_t)(XT - 1) * XSC * XSC + i2 * 4);
        }
        if (tid < 24) {
            const int q = tid / 12, i2 = tid % 12;
            cpa16(SPq(q) + i2 * 4, Pb[q] + (size_t)(XT - 1) * XSC + i2 * 4);
        }
        cpa_commit();
    }
    __syncthreads();

    // nominal trajectories (warp 0 -> b0, warp 1 -> b1)
    if (tid < 64) {
        const int q = tid >> 5;
        float* scx = SCXq(q);
        scx[lane] = Xi[(b0 + q) * 32 + lane];
        for (int t = 1; t < XT; t++) {
            __syncwarp();
            float acc = 0.f;
            #pragma unroll
            for (int jj = 0; jj < 32; jj++) {
                int j = (lane + jj) & 31;
                acc += sF[lane * 48 + j] * scx[(t - 1) * 32 + j];
            }
            scx[t * 32 + lane] = acc;
        }
    }
    __syncthreads();

    // =============== backward Riccati (both batches per barrier interval) =====
    for (int t = XT - 1; t >= 0; t--) {
        // A: M = V @ F, q-loop (192 thr, 4x2)
        #pragma unroll
        for (int q = 0; q < 2; q++) {
            if (tid < 192) {
                const float* sV = SVq(q);
                float* sM = SMq(q);
                const int s0 = (tid / 24) * 4, j0 = (tid % 24) * 2;
                float a00=0,a01=0,a10=0,a11=0,a20=0,a21=0,a30=0,a31=0;
                #pragma unroll 8
                for (int r = 0; r < 32; r++) {
                    const float4 vv = *(const float4*)(sV + r * 36 + s0);
                    const float2 ff = *(const float2*)(sF + r * 48 + j0);
                    a00 += vv.x*ff.x; a01 += vv.x*ff.y; a10 += vv.y*ff.x; a11 += vv.y*ff.y;
                    a20 += vv.z*ff.x; a21 += vv.z*ff.y; a30 += vv.w*ff.x; a31 += vv.w*ff.y;
                }
                *(float2*)(sM + (s0+0)*48 + j0) = make_float2(a00,a01);
                *(float2*)(sM + (s0+1)*48 + j0) = make_float2(a10,a11);
                *(float2*)(sM + (s0+2)*48 + j0) = make_float2(a20,a21);
                *(float2*)(sM + (s0+3)*48 + j0) = make_float2(a30,a31);
            }
        }
        cpa_wait0();
        __syncthreads();                            // Qraw(t), p(t), M ready (both q)

        // B: Qt = Qraw + F^T M (84 thr float4, q-loop)  ||  qt+cost (208-255, q-loop)
        #pragma unroll
        for (int q = 0; q < 2; q++) {
            if (tid < 84) {
                const float* sQraw = SQRq(q);
                const float* sM = SMq(q);
                float* sQt = SQTq(q);
                const int i0 = i0B, j0 = j0B;
                float4 c0 = *(const float4*)(sQraw + (i0+0)*48 + j0);
                float4 c1 = *(const float4*)(sQraw + (i0+1)*48 + j0);
                float4 c2 = *(const float4*)(sQraw + (i0+2)*48 + j0);
                float4 c3 = *(const float4*)(sQraw + (i0+3)*48 + j0);
                #pragma unroll 4
                for (int s = 0; s < 32; s++) {
                    const float4 fa = *(const float4*)(sF + s * 48 + i0);
                    const float4 mb = *(const float4*)(sM + s * 48 + j0);
                    c0.x += fa.x*mb.x; c0.y += fa.x*mb.y; c0.z += fa.x*mb.z; c0.w += fa.x*mb.w;
                    c1.x += fa.y*mb.x; c1.y += fa.y*mb.y; c1.z += fa.y*mb.z; c1.w += fa.y*mb.w;
                    c2.x += fa.z*mb.x; c2.y += fa.z*mb.y; c2.z += fa.z*mb.z; c2.w += fa.z*mb.w;
                    c3.x += fa.w*mb.x; c3.y += fa.w*mb.y; c3.z += fa.w*mb.z; c3.w += fa.w*mb.w;
                }
                *(float4*)(sQt + (i0+0)*48 + j0) = c0;
                *(float4*)(sQt + (i0+1)*48 + j0) = c1;
                *(float4*)(sQt + (i0+2)*48 + j0) = c2;
                *(float4*)(sQt + (i0+3)*48 + j0) = c3;
            } else if (tid >= 208) {
                const float* sQraw = SQRq(q);
                const float* scx = SCXq(q);
                const float* sv = SVvq(q);
                const float* sp = SPq(q);
                const int i = tid - 208;
                float tmp = 0.f;                    // (Qraw_x* . cx)_i
                #pragma unroll
                for (int jj = 0; jj < 32; jj++) {
                    int j = (i + jj) & 31;
                    tmp += sQraw[i * 48 + j] * scx[t * 32 + j];
                }
                float acc = sp[i] + tmp;
                #pragma unroll
                for (int s = 0; s < 32; s++) acc += sv[s] * sF[s * 48 + i];
                SQtvq(q)[i] = acc;
                if (i < 32)
                    SCCq(q)[i] += scx[t * 32 + i] * (0.5f * tmp + sp[i]);
            }
        }
        __syncthreads();                            // Qt(lower+uu), qt ready; Qraw free

        // C: prefetch next Q,p (both)  +  2-warp GJ inverses  +  mirrors (64-183)
        if (t > 0) {
            for (int idx = tid; idx < 1152; idx += 256) {
                const int q = idx / 576, i2 = idx % 576;
                cpa16(SQRq(q) + i2 * 4, Qb[q] + (size_t)(t - 1) * XSC * XSC + i2 * 4);
            }
            if (tid < 24) {
                const int q = tid / 12, i2 = tid % 12;
                cpa16(SPq(q) + i2 * 4, Pb[q] + (size_t)(t - 1) * XSC + i2 * 4);
            }
            cpa_commit();
        }
        if (tid < 64) {                             // warp w inverts Quu of batch w
            const int q = tid >> 5;
            const float* sQt = SQTq(q);
            float* sInv = SINVq(q);
            const int col = lane & 15;
            float creg[16];
            if (lane < 16) {
                #pragma unroll
                for (int i2 = 0; i2 < 16; i2++) creg[i2] = sQt[(32+i2)*48 + 32 + lane];
            } else {
                #pragma unroll
                for (int i2 = 0; i2 < 16; i2++) creg[i2] = (i2 == col) ? 1.f : 0.f;
            }
            #pragma unroll
            for (int k = 0; k < 16; k++) {
                const float ck  = __shfl_sync(0xffffffffu, creg[k], k);
                const float piv = 1.0f / ck;
                creg[k] *= piv;
                #pragma unroll
                for (int i2 = 0; i2 < 16; i2++) {
                    if (i2 == k) continue;
                    const float cik = __shfl_sync(0xffffffffu, creg[i2], k);
                    creg[i2] -= cik * creg[k];
                }
            }
            if (lane >= 16) {
                #pragma unroll
                for (int i2 = 0; i2 < 16; i2++) sInv[i2 * 20 + col] = creg[i2];
            }
        } else if (tid < 184) {                     // mirrors: q0 on 64-123, q1 on 124-183
            float* sQt = SQTq((tid - 64) / 60);
            const float4 v0 = *(const float4*)(sQt + mSrc + 0*48);
            const float4 v1 = *(const float4*)(sQt + mSrc + 1*48);
            const float4 v2 = *(const float4*)(sQt + mSrc + 2*48);
            const float4 v3 = *(const float4*)(sQt + mSrc + 3*48);
            *(float4*)(sQt + mDst + 0*48) = make_float4(v0.x, v1.x, v2.x, v3.x);
            *(float4*)(sQt + mDst + 1*48) = make_float4(v0.y, v1.y, v2.y, v3.y);
            *(float4*)(sQt + mDst + 2*48) = make_float4(v0.z, v1.z, v2.z, v3.z);
            *(float4*)(sQt + mDst + 3*48) = make_float4(v0.w, v1.w, v2.w, v3.w);
        }
        __syncthreads();                            // Inv + full symmetric Qt (both)

        // D: Kt/kt for both batches on disjoint warps
        if (tid < 32)        kt_tile(SINVq(0), SQTq(0), SKTq(0), tid);
        else if (tid < 48)   kt_vec (SINVq(0), SQtvq(0), SKtq(0), SCCq(0), tid - 32);
        else if (tid >= 64 && tid < 96)
                             kt_tile(SINVq(1), SQTq(1), SKTq(1), tid - 64);
        else if (tid >= 96 && tid < 112)
                             kt_vec (SINVq(1), SQtvq(1), SKtq(1), SCCq(1), tid - 96);
        __syncthreads();                            // Kt, kt ready (both)

        // E: Vn/vn/gains for both batches on disjoint thread ranges
        if (tid < 64) {
            vn_tile(SQTq(0), SKTq(0), SVq(0), tid);
        } else if (tid < 96) {
            const int i = tid - 64;
            const float* sQt = SQTq(0);
            const float* skt = SKtq(0);
            float acc = SQtvq(0)[i];
            #pragma unroll
            for (int aa = 0; aa < 16; aa++) {
                int a = (i + aa) & 15;
                acc += sQt[i*48 + 32 + a] * skt[a];
            }
            SVvq(0)[i] = acc;
        } else if (tid < 128) {
            float* gdst = g_G + ((size_t)(b0+0) * XT + t) * 528;
            const float* sKt = SKTq(0);
            const float* skt = SKtq(0);
            for (int e = tid - 96; e < 132; e += 32) {
                float4 val;
                if (e < 128) val = *(const float4*)(sKt + e * 4);
                else         val = *(const float4*)(skt + (e - 128) * 4);
                *(float4*)(gdst + e * 4) = val;
            }
        } else if (tid < 192) {
            vn_tile(SQTq(1), SKTq(1), SVq(1), tid - 128);
        } else if (tid < 224) {
            const int i = tid - 192;
            const float* sQt = SQTq(1);
            const float* skt = SKtq(1);
            float acc = SQtvq(1)[i];
            #pragma unroll
            for (int aa = 0; aa < 16; aa++) {
                int a = (i + aa) & 15;
                acc += sQt[i*48 + 32 + a] * skt[a];
            }
            SVvq(1)[i] = acc;
        } else {
            float* gdst = g_G + ((size_t)(b0+1) * XT + t) * 528;
            const float* sKt = SKTq(1);
            const float* skt = SKtq(1);
            for (int e = tid - 224; e < 132; e += 32) {
                float4 val;
                if (e < 128) val = *(const float4*)(sKt + e * 4);
                else         val = *(const float4*)(skt + (e - 128) * 4);
                *(float4*)(gdst + e * 4) = val;
            }
        }
        __syncthreads();                            // V, v ready for next step
    }

    // ---- cost writes (idle threads) run concurrently with forward rollouts ----
    if (tid == 64 || tid == 65) {
        const int q = tid - 64;
        const float* scc = SCCq(q);
        float c = 0.f;
        #pragma unroll
        for (int i = 0; i < 48; i++) c += scc[i];
        out[(size_t)XNB * XT * XNS + (size_t)XNB * XT * XNC + (b0 + q)] = c;
    }

    // ====== forward rollouts: warp 0 -> b0, warp 1 -> b1 (shuffle-resident) ====
    if (tid < 64) {
        const int q = tid >> 5;
        const int bq = b0 + q;
        const float* scx = SCXq(q);
        float* kb0 = SMq(q);
        float* kb1 = SMq(q) + 544;
        float* out_x = out;
        float* out_u = out + (size_t)XNB * XT * XNS;
        float x = Xi[bq * 32 + lane];
        {
            const float* src = g_G + (size_t)bq * XT * 528;
            #pragma unroll
            for (int kk = 0; kk < 5; kk++) {
                int e = lane + kk * 32;
                if (e < 132) cpa16(kb0 + e * 4, src + e * 4);
            }
            cpa_commit();
        }
        int pb = 0;
        for (int t = 0; t < XT; t++) {
            cpa_wait0();
            __syncwarp();
            const float* kc = pb ? kb1 : kb0;
            const float d = x - scx[t * 32 + lane];
            float acc = 0.f;
            #pragma unroll
            for (int jj = 0; jj < 32; jj++) {
                int j = (lane + jj) & 31;
                float dj = __shfl_sync(0xffffffffu, d, j);
                if (lane < 16) acc += kc[lane * 32 + j] * dj;
            }
            float u = 0.f;
            if (lane < 16) {
                u = acc + kc[512 + lane];
                out_u[((size_t)bq * XT + t) * XNC + lane] = u;
            }
            out_x[((size_t)bq * XT + t) * XNS + lane] = x;
            if (t + 1 < XT) {
                const float* src = g_G + ((size_t)bq * XT + t + 1) * 528;
                float* kn = pb ? kb0 : kb1;
                #pragma unroll
                for (int kk = 0; kk < 5; kk++) {
                    int e = lane + kk * 32;
                    if (e < 132) cpa16(kn + e * 4, src + e * 4);
                }
                cpa_commit();
            }
            float xn = 0.f, xn2 = 0.f;
            #pragma unroll
            for (int jj = 0; jj < 32; jj++) {
                int j = (lane + jj) & 31;
                float xj = __shfl_sync(0xffffffffu, x, j);
                if (jj & 1) xn2 += sF[lane * 48 + j] * xj;
                else        xn  += sF[lane * 48 + j] * xj;
            }
            #pragma unroll
            for (int aa = 0; aa < 16; aa++) {
                int a2 = (lane + aa) & 15;
                float ua = __shfl_sync(0xffffffffu, u, a2);
                if (aa & 1) xn2 += sF[lane * 48 + 32 + a2] * ua;
                else        xn  += sF[lane * 48 + 32 + a2] * ua;
            }
            x = xn + xn2;
            pb ^= 1;
        }
    }
}

extern "C" void kernel_launch(void* const* d_in, const int* in_sizes, int n_in,
                              void* d_out, int out_size) {
    const float* x_init = (const float*)d_in[0];
    const float* Q      = (const float*)d_in[1];
    const float* p      = (const float*)d_in[2];
    const float* A      = (const float*)d_in[3];
    const float* B      = (const float*)d_in[4];
    float* out = (float*)d_out;
    cudaFuncSetAttribute(lqr_kernel,
                         cudaFuncAttributeMaxDynamicSharedMemorySize, SMEM_BYTES);
    lqr_kernel<<<XNB / 2, 256, SMEM_BYTES>>>(x_init, Q, p, A, B, out);
}